// round 1
// baseline (speedup 1.0000x reference)
#include <cuda_runtime.h>
#include <cstdint>

// ScoreMatching: B=2048 (from in_sizes), D=64, H=512, fp32.
// val[b] = 0.5*||s_b||^2 + tr(J_b),  J = W4 D3 W3 D2 W2 D1 W1 (D_k = diag(relu' masks))
//
// Plan: one CTA per sample, fully fused.
//  - prep kernel transposes W1,W2,W3 into __device__ scratch for coalesced loads
//  - forward MLP -> h/masks in SMEM
//  - Jacobian chain in two d-halves of 32:
//      smA = m1 (*) W1[:, d0:d0+32]      (masked T0 slice, SMEM)
//      smB = m2 (*) (W2 @ smA)           (T1 slice, SMEM, FFMA2 GEMM)
//      div += sum_j m3[j] * sum_d (W3 @ smB)[j,d] * W4[d0+d, j]   (T2 never stored)
//  - fp32x2 packed FMA (fma.rn.f32x2) for 128 MAC/cyc/SM

#define DD   64
#define HH   512
#define DB   32
#define BROW 36          // 32 + 4 pad floats per SMEM row (bank-conflict-free STS.128)
#define NT   256         // threads per CTA; each owns rows (tid, tid+256)

typedef unsigned long long ull;

__device__ float g_W1T[DD * HH];   // W1T[d*512 + i] = W1[i*64 + d]
__device__ float g_W2T[HH * HH];   // W2T[k*512 + i] = W2[i*512 + k]
__device__ float g_W3T[HH * HH];

__device__ __forceinline__ ull ffma2(ull a, ull b, ull c) {
    ull d;
    asm("fma.rn.f32x2 %0, %1, %2, %3;" : "=l"(d) : "l"(a), "l"(b), "l"(c));
    return d;
}
__device__ __forceinline__ ull dup2(float w) {
    ull r;
    unsigned int u = __float_as_uint(w);
    asm("mov.b64 %0, {%1, %1};" : "=l"(r) : "r"(u));
    return r;
}
__device__ __forceinline__ ull pack2(float a, float b) {
    ull r;
    asm("mov.b64 %0, {%1, %2};" : "=l"(r) : "r"(__float_as_uint(a)), "r"(__float_as_uint(b)));
    return r;
}
__device__ __forceinline__ float2 unpack2(ull v) {
    unsigned int lo, hi;
    asm("mov.b64 {%0, %1}, %2;" : "=r"(lo), "=r"(hi) : "l"(v));
    return make_float2(__uint_as_float(lo), __uint_as_float(hi));
}

// rank-1 update on two output rows sharing one broadcast SMEM row (32 d-cols).
__device__ __forceinline__ void rank1_2(ull* accA, ull* accB, float wA, float wB,
                                        const float* __restrict__ brow) {
    ull wdA = dup2(wA), wdB = dup2(wB);
    const ulonglong2* b2p = (const ulonglong2*)brow;
#pragma unroll
    for (int q = 0; q < 8; q++) {
        ulonglong2 bb = b2p[q];
        accA[2 * q]     = ffma2(wdA, bb.x, accA[2 * q]);
        accA[2 * q + 1] = ffma2(wdA, bb.y, accA[2 * q + 1]);
        accB[2 * q]     = ffma2(wdB, bb.x, accB[2 * q]);
        accB[2 * q + 1] = ffma2(wdB, bb.y, accB[2 * q + 1]);
    }
}

// -------- prep: tiled transpose of W1, W2, W3 into __device__ scratch --------
__global__ void prep_transpose(const float* __restrict__ W1,
                               const float* __restrict__ W2,
                               const float* __restrict__ W3) {
    __shared__ float tile[32][33];
    int z = blockIdx.z;
    const float* src = (z == 0) ? W1 : (z == 1) ? W2 : W3;
    float* dst       = (z == 0) ? g_W1T : (z == 1) ? g_W2T : g_W3T;
    int R = HH;                       // source rows
    int C = (z == 0) ? DD : HH;       // source cols
    int c0 = blockIdx.x * 32, r0 = blockIdx.y * 32;
    if (c0 >= C || r0 >= R) return;
    int tx = threadIdx.x, ty = threadIdx.y;
#pragma unroll
    for (int j = ty; j < 32; j += 8)
        tile[j][tx] = src[(size_t)(r0 + j) * C + c0 + tx];
    __syncthreads();
#pragma unroll
    for (int j = ty; j < 32; j += 8)
        dst[(size_t)(c0 + j) * R + r0 + tx] = tile[tx][j];
}

// ------------------------------- main kernel --------------------------------
__global__ void __launch_bounds__(NT, 1)
score_kernel(const float* __restrict__ x,
             const float* __restrict__ b1, const float* __restrict__ b2,
             const float* __restrict__ b3,
             const float* __restrict__ W4, const float* __restrict__ b4,
             float* __restrict__ out) {
    extern __shared__ float sm[];
    float* xs  = sm;                  // 64
    float* h1  = sm + 64;             // 512
    float* m1  = h1 + HH;             // 512
    float* h2  = m1 + HH;             // 512
    float* m2  = h2 + HH;             // 512
    float* h3  = m2 + HH;             // 512
    float* m3  = h3 + HH;             // 512
    float* sq  = m3 + HH;             // 64  (0.5*s_d^2)
    float* red = sq + DD;             // 32
    float* smA = red + 32;            // 512*36  masked-W1 / GEMM-B operand
    float* smB = smA + HH * BROW;     // 512*36  T1 slice

    const int tid = threadIdx.x;
    const int b   = blockIdx.x;
    const int r0i = tid, r1i = tid + 256;

    if (tid < DD) xs[tid] = x[(size_t)b * DD + tid];
    __syncthreads();

    // ---- layer 1: a1 = W1 x + b1 (via W1T, coalesced) ----
    {
        float a0 = 0.f, a1v = 0.f;
#pragma unroll
        for (int k = 0; k < DD; k++) {
            float hv = xs[k];
            a0  = fmaf(g_W1T[k * HH + r0i], hv, a0);
            a1v = fmaf(g_W1T[k * HH + r1i], hv, a1v);
        }
        a0 += b1[r0i]; a1v += b1[r1i];
        h1[r0i] = a0  > 0.f ? a0  : 0.f;  m1[r0i] = a0  > 0.f ? 1.f : 0.f;
        h1[r1i] = a1v > 0.f ? a1v : 0.f;  m1[r1i] = a1v > 0.f ? 1.f : 0.f;
    }
    __syncthreads();

    // ---- layer 2 ----
    {
        float a0 = 0.f, a1v = 0.f;
#pragma unroll 8
        for (int k = 0; k < HH; k++) {
            float hv = h1[k];
            a0  = fmaf(g_W2T[(size_t)k * HH + r0i], hv, a0);
            a1v = fmaf(g_W2T[(size_t)k * HH + r1i], hv, a1v);
        }
        a0 += b2[r0i]; a1v += b2[r1i];
        h2[r0i] = a0  > 0.f ? a0  : 0.f;  m2[r0i] = a0  > 0.f ? 1.f : 0.f;
        h2[r1i] = a1v > 0.f ? a1v : 0.f;  m2[r1i] = a1v > 0.f ? 1.f : 0.f;
    }
    __syncthreads();

    // ---- layer 3 ----
    {
        float a0 = 0.f, a1v = 0.f;
#pragma unroll 8
        for (int k = 0; k < HH; k++) {
            float hv = h2[k];
            a0  = fmaf(g_W3T[(size_t)k * HH + r0i], hv, a0);
            a1v = fmaf(g_W3T[(size_t)k * HH + r1i], hv, a1v);
        }
        a0 += b3[r0i]; a1v += b3[r1i];
        h3[r0i] = a0  > 0.f ? a0  : 0.f;  m3[r0i] = a0  > 0.f ? 1.f : 0.f;
        h3[r1i] = a1v > 0.f ? a1v : 0.f;  m3[r1i] = a1v > 0.f ? 1.f : 0.f;
    }
    __syncthreads();

    // ---- s = W4 h3 + b4 ; sq[d] = 0.5 s_d^2 ----
    if (tid < DD) {
        const float4* w = (const float4*)(W4 + (size_t)tid * HH);
        ull acc0 = 0ull, acc1 = 0ull;
        const float4* hv4 = (const float4*)h3;
#pragma unroll 8
        for (int q = 0; q < HH / 4; q++) {
            float4 a = w[q], hv = hv4[q];
            acc0 = ffma2(pack2(a.x, a.y), pack2(hv.x, hv.y), acc0);
            acc1 = ffma2(pack2(a.z, a.w), pack2(hv.z, hv.w), acc1);
        }
        float2 p0 = unpack2(acc0), p1 = unpack2(acc1);
        float s = p0.x + p0.y + p1.x + p1.y + b4[tid];
        sq[tid] = 0.5f * s * s;
    }
    __syncthreads();

    // ---- Jacobian trace over two d-halves ----
    float div_acc = 0.f;
#pragma unroll 1
    for (int d0 = 0; d0 < DD; d0 += DB) {
        // stage smA[i][dd] = m1[i] * W1[i][d0+dd]   (coalesced via W1T)
        for (int idx = tid; idx < HH * DB; idx += NT) {
            int dd = idx >> 9;          // 0..31
            int i  = idx & (HH - 1);    // 0..511
            smA[i * BROW + dd] = m1[i] * g_W1T[(size_t)(d0 + dd) * HH + i];
        }
        __syncthreads();

        // GEMM1: smB = m2 (*) (W2 @ smA)
        {
            ull accA[16], accB[16];
#pragma unroll
            for (int q = 0; q < 16; q++) { accA[q] = 0ull; accB[q] = 0ull; }
#pragma unroll 4
            for (int k = 0; k < HH; k++) {
                float wA = g_W2T[(size_t)k * HH + r0i];
                float wB = g_W2T[(size_t)k * HH + r1i];
                rank1_2(accA, accB, wA, wB, smA + k * BROW);
            }
            float mA = m2[r0i], mB = m2[r1i];
            float4* dA = (float4*)(smB + r0i * BROW);
            float4* dB = (float4*)(smB + r1i * BROW);
#pragma unroll
            for (int q = 0; q < 8; q++) {
                float2 u = unpack2(accA[2 * q]), v = unpack2(accA[2 * q + 1]);
                dA[q] = make_float4(u.x * mA, u.y * mA, v.x * mA, v.y * mA);
                float2 uu = unpack2(accB[2 * q]), vv = unpack2(accB[2 * q + 1]);
                dB[q] = make_float4(uu.x * mB, uu.y * mB, vv.x * mB, vv.y * mB);
            }
        }
        __syncthreads();

        // GEMM2 + fold into div: rows j of m3 (*) (W3 @ smB), dotted with W4[:, j]
        {
            ull accA[16], accB[16];
#pragma unroll
            for (int q = 0; q < 16; q++) { accA[q] = 0ull; accB[q] = 0ull; }
#pragma unroll 4
            for (int k = 0; k < HH; k++) {
                float wA = g_W3T[(size_t)k * HH + r0i];
                float wB = g_W3T[(size_t)k * HH + r1i];
                rank1_2(accA, accB, wA, wB, smB + k * BROW);
            }
            float mA = m3[r0i], mB = m3[r1i];
            float lA = 0.f, lB = 0.f;
#pragma unroll
            for (int q = 0; q < 16; q++) {
                float2 u = unpack2(accA[q]);
                float2 v = unpack2(accB[q]);
                const float* w4a = W4 + (size_t)(d0 + 2 * q) * HH;
                const float* w4b = W4 + (size_t)(d0 + 2 * q + 1) * HH;
                lA += u.x * w4a[r0i] + u.y * w4b[r0i];
                lB += v.x * w4a[r1i] + v.y * w4b[r1i];
            }
            div_acc += mA * lA + mB * lB;
        }
        __syncthreads();
    }

    // ---- reduce div over block, add 0.5||s||^2 ----
    float v = div_acc;
#pragma unroll
    for (int off = 16; off; off >>= 1) v += __shfl_down_sync(0xffffffffu, v, off);
    if ((tid & 31) == 0) red[tid >> 5] = v;
    __syncthreads();
    if (tid == 0) {
        float t = 0.f;
#pragma unroll
        for (int w = 0; w < NT / 32; w++) t += red[w];
#pragma unroll
        for (int d = 0; d < DD; d++) t += sq[d];
        out[b] = t;
    }
}

// ------------------------------- launcher -----------------------------------
extern "C" void kernel_launch(void* const* d_in, const int* in_sizes, int n_in,
                              void* d_out, int out_size) {
    const float* x  = (const float*)d_in[0];
    const float* W1 = (const float*)d_in[1];
    const float* b1 = (const float*)d_in[2];
    const float* W2 = (const float*)d_in[3];
    const float* b2 = (const float*)d_in[4];
    const float* W3 = (const float*)d_in[5];
    const float* b3 = (const float*)d_in[6];
    const float* W4 = (const float*)d_in[7];
    const float* b4 = (const float*)d_in[8];
    float* out = (float*)d_out;

    int B = in_sizes[0] / DD;

    // transpose W1, W2, W3 into __device__ scratch (graph-capturable kernel)
    prep_transpose<<<dim3(16, 16, 3), dim3(32, 8)>>>(W1, W2, W3);

    const size_t smem = (size_t)(64 + 6 * HH + DD + 32 + 2 * HH * BROW) * sizeof(float);
    cudaFuncSetAttribute(score_kernel, cudaFuncAttributeMaxDynamicSharedMemorySize, (int)smem);
    score_kernel<<<B, NT, smem>>>(x, b1, b2, b3, W4, b4, out);
}